// round 15
// baseline (speedup 1.0000x reference)
#include <cuda_runtime.h>
#include <math.h>

#define Hh   16
#define DU   64
#define DP   32
#define Dd   96
#define Bn   16
#define TCACHE 4095
#define TT   4096
#define WIN  512
#define Fdim 1536

#define SPLIT  2
#define ROWS_B (WIN / SPLIT)      // 256 rows per stream CTA
#define ITER_B (ROWS_B / 8 / 4)   // iterations per warp (8 warps, 4 rows/iter)

__device__ float g_qt[Bn * Hh][104];            // [0..95]=qt (pre-scaled), [96]=const
__device__ float g_pl[Bn * Hh * SPLIT];         // partial l
__device__ float g_pacc[Bn * Hh * SPLIT][Dd];   // partial acc

// ---------------- Kernel A: q projection + K-fold, batched over all b per head ----
// One CTA per head. Weight columns are loaded once and applied to 8 batches per
// thread (8 independent accumulators -> pipelined FMA, no latency exposure).
__global__ __launch_bounds__(256)
void prep_kernel(const float* __restrict__ content,
                 const float* __restrict__ Wq_u, const float* __restrict__ bq_u,
                 const float* __restrict__ Wk_u, const float* __restrict__ bk_u,
                 const float* __restrict__ Wq_p, const float* __restrict__ bq_p,
                 const float* __restrict__ Wk_p, const float* __restrict__ bk_p)
{
    const int h   = blockIdx.x;
    const int tid = threadIdx.x;

    __shared__ float s_u[Bn][Dd];   // u|p slice for every batch
    __shared__ float s_q[Bn][Dd];   // q for every batch

    // load current-token slices for all 16 batches (coalesced per 96-run)
    for (int idx = tid; idx < Bn * Dd; idx += 256) {
        int b = idx / Dd, d = idx % Dd;
        s_u[b][d] = content[(size_t)b * Fdim + h * Dd + d];
    }
    __syncthreads();

    const int e  = tid % Dd;        // output index 0..95
    const int bh = tid / Dd;        // batch half 0..1 (tid<192), else idle
    const int b0 = bh * 8;

    // ---- stage 1: q[b][e] = bq[e] + sum_d u[b][d] * Wq[d][e] ----
    if (tid < 192) {
        float acc[8];
        if (e < DU) {
            const float* Wc = Wq_u + ((size_t)h * DU) * DU + e;
            float bias = bq_u[h * DU + e];
            #pragma unroll
            for (int k = 0; k < 8; k++) acc[k] = bias;
            #pragma unroll 8
            for (int d = 0; d < DU; d++) {
                float wv = Wc[d * DU];
                #pragma unroll
                for (int k = 0; k < 8; k++) acc[k] = fmaf(s_u[b0 + k][d], wv, acc[k]);
            }
        } else {
            int ep = e - DU;
            const float* Wc = Wq_p + ((size_t)h * DP) * DP + ep;
            float bias = bq_p[h * DP + ep];
            #pragma unroll
            for (int k = 0; k < 8; k++) acc[k] = bias;
            #pragma unroll 8
            for (int d = 0; d < DP; d++) {
                float wv = Wc[d * DP];
                #pragma unroll
                for (int k = 0; k < 8; k++) acc[k] = fmaf(s_u[b0 + k][DU + d], wv, acc[k]);
            }
        }
        #pragma unroll
        for (int k = 0; k < 8; k++) s_q[b0 + k][e] = acc[k];
    }
    __syncthreads();

    // ---- stage 2: qt[b][d] = inv * sum_e Wk[d][e] * q[b][e]  (row reads, contiguous) ----
    const float inv = 1.0f / sqrtf((float)Dd);
    if (tid < 192) {
        const int d = e;            // reuse mapping: output dim 0..95
        float acc[8];
        #pragma unroll
        for (int k = 0; k < 8; k++) acc[k] = 0.f;
        if (d < DU) {
            const float4* Wr = (const float4*)(Wk_u + ((size_t)h * DU + d) * DU);
            #pragma unroll
            for (int e4 = 0; e4 < DU / 4; e4++) {
                float4 wv = Wr[e4];
                #pragma unroll
                for (int k = 0; k < 8; k++) {
                    const float* qb = s_q[b0 + k];
                    acc[k] = fmaf(wv.x, qb[e4*4],   acc[k]);
                    acc[k] = fmaf(wv.y, qb[e4*4+1], acc[k]);
                    acc[k] = fmaf(wv.z, qb[e4*4+2], acc[k]);
                    acc[k] = fmaf(wv.w, qb[e4*4+3], acc[k]);
                }
            }
        } else {
            int dp = d - DU;
            const float4* Wr = (const float4*)(Wk_p + ((size_t)h * DP + dp) * DP);
            #pragma unroll
            for (int e4 = 0; e4 < DP / 4; e4++) {
                float4 wv = Wr[e4];
                #pragma unroll
                for (int k = 0; k < 8; k++) {
                    const float* qb = s_q[b0 + k] + DU;
                    acc[k] = fmaf(wv.x, qb[e4*4],   acc[k]);
                    acc[k] = fmaf(wv.y, qb[e4*4+1], acc[k]);
                    acc[k] = fmaf(wv.z, qb[e4*4+2], acc[k]);
                    acc[k] = fmaf(wv.w, qb[e4*4+3], acc[k]);
                }
            }
        }
        #pragma unroll
        for (int k = 0; k < 8; k++) g_qt[(b0 + k) * Hh + h][d] = acc[k] * inv;
    } else if (tid < 192 + Bn) {
        // ---- const term: (q[b] . bk) * inv, one thread per batch ----
        int b = tid - 192;
        float acc = 0.f;
        for (int ee = 0; ee < DU; ee++) acc = fmaf(s_q[b][ee],      bk_u[h * DU + ee], acc);
        for (int ee = 0; ee < DP; ee++) acc = fmaf(s_q[b][DU + ee], bk_p[h * DP + ee], acc);
        g_qt[b * Hh + h][Dd] = acc * inv;
    }
}

// ---------------- Kernel B: streaming attention over a window split ----------------
__global__ __launch_bounds__(256, 4)
void stream_kernel(const float* __restrict__ content,
                   const float* __restrict__ cache,
                   const float* __restrict__ pos_param_p)
{
    const int h     = blockIdx.x;
    const int b     = blockIdx.y;
    const int split = blockIdx.z;
    const int tid   = threadIdx.x;
    const int lane  = tid & 31;
    const int w     = tid >> 5;
    const int qq    = lane >> 3;
    const int s     = lane & 7;
    const int s4    = s * 4;

    __shared__ alignas(16) float s_qt[104];
    __shared__ float s_bias[ROWS_B];
    __shared__ float s_gl[32];
    __shared__ alignas(16) float s_gacc[32][Dd];

    const float pp = *pos_param_p;

    if (tid < 97) s_qt[tid] = g_qt[b * Hh + h][tid];

    // bias for this split's rows (time_mask is a uniform shift -> ignored)
    for (int p = tid; p < ROWS_B; p += 256) {
        int n = (WIN - 1) - (split * ROWS_B + p);
        float bucket;
        if (n < 16)        bucket = (float)n;
        else if (n >= 113) bucket = 31.0f;
        else {
            int bb = 16 + (int)(__logf((float)n * 0.0625f) * 7.69365658f);
            bucket = (float)bb;
        }
        s_bias[p] = -pp * bucket;
    }
    __syncthreads();

    const float4* q4 = (const float4*)s_qt;
    const float4  qtA = q4[s], qtB = q4[8 + s], qtC = q4[16 + s];
    const float   sc  = s_qt[Dd];
    const float*  crow  = content + (size_t)b * Fdim + h * Dd;
    const float*  cbase = cache   + ((size_t)b * TCACHE) * Fdim + h * Dd;
    const int     base  = (TT - WIN) + split * ROWS_B + w * (ROWS_B / 8);

    float l = 0.f;
    float4 aA = {0,0,0,0}, aB = {0,0,0,0}, aC = {0,0,0,0};

    const float* r0;
    {
        int j = base + qq;
        r0 = (j < TCACHE) ? (cbase + (size_t)j * Fdim) : crow;
    }
    float4 nva = *(const float4*)(r0 + s4);
    float4 nvb = *(const float4*)(r0 + 32 + s4);
    float4 nvc = *(const float4*)(r0 + 64 + s4);

    #pragma unroll 2
    for (int i = 0; i < ITER_B; i++) {
        float4 va = nva, vb = nvb, vc = nvc;
        if (i < ITER_B - 1) {
            int j = base + (i + 1) * 4 + qq;
            const float* r = (j < TCACHE) ? (cbase + (size_t)j * Fdim) : crow;
            nva = *(const float4*)(r + s4);
            nvb = *(const float4*)(r + 32 + s4);
            nvc = *(const float4*)(r + 64 + s4);
        }
        float x;
        x = va.x * qtA.x;          x = fmaf(va.y, qtA.y, x);
        x = fmaf(va.z, qtA.z, x);  x = fmaf(va.w, qtA.w, x);
        x = fmaf(vb.x, qtB.x, x);  x = fmaf(vb.y, qtB.y, x);
        x = fmaf(vb.z, qtB.z, x);  x = fmaf(vb.w, qtB.w, x);
        x = fmaf(vc.x, qtC.x, x);  x = fmaf(vc.y, qtC.y, x);
        x = fmaf(vc.z, qtC.z, x);  x = fmaf(vc.w, qtC.w, x);
        x += __shfl_xor_sync(0xffffffffu, x, 1);
        x += __shfl_xor_sync(0xffffffffu, x, 2);
        x += __shfl_xor_sync(0xffffffffu, x, 4);

        float e = __expf(x + sc + s_bias[w * (ROWS_B / 8) + i * 4 + qq]);
        l += e;
        aA.x = fmaf(e, va.x, aA.x); aA.y = fmaf(e, va.y, aA.y);
        aA.z = fmaf(e, va.z, aA.z); aA.w = fmaf(e, va.w, aA.w);
        aB.x = fmaf(e, vb.x, aB.x); aB.y = fmaf(e, vb.y, aB.y);
        aB.z = fmaf(e, vb.z, aB.z); aB.w = fmaf(e, vb.w, aB.w);
        aC.x = fmaf(e, vc.x, aC.x); aC.y = fmaf(e, vc.y, aC.y);
        aC.z = fmaf(e, vc.z, aC.z); aC.w = fmaf(e, vc.w, aC.w);
    }

    const int g = (w << 2) | qq;
    if (s == 0) s_gl[g] = l;
    *(float4*)&s_gacc[g][s4]      = aA;
    *(float4*)&s_gacc[g][32 + s4] = aB;
    *(float4*)&s_gacc[g][64 + s4] = aC;
    __syncthreads();

    const int bh = (b * Hh + h) * SPLIT + split;
    if (tid < Dd) {
        float a = 0.f;
        #pragma unroll
        for (int gg = 0; gg < 32; gg++) a += s_gacc[gg][tid];
        g_pacc[bh][tid] = a;
    } else if (tid == Dd) {
        float L = 0.f;
        #pragma unroll
        for (int gg = 0; gg < 32; gg++) L += s_gl[gg];
        g_pl[bh] = L;
    }
}

// ---------------- Kernel C: combine + V-projection + residual ----------------
__global__ __launch_bounds__(128)
void combine_kernel(const float* __restrict__ content,
                    const float* __restrict__ Wv_u, const float* __restrict__ bv_u,
                    const float* __restrict__ Wv_p, const float* __restrict__ bv_p,
                    float* __restrict__ out)
{
    const int h   = blockIdx.x;
    const int b   = blockIdx.y;
    const int tid = threadIdx.x;

    __shared__ float s_cbar[Dd];

    const int bh0 = (b * Hh + h) * SPLIT;
    if (tid < Dd) {
        float a = 0.f, L = 0.f;
        #pragma unroll
        for (int sp = 0; sp < SPLIT; sp++) a += g_pacc[bh0 + sp][tid];
        #pragma unroll
        for (int sp = 0; sp < SPLIT; sp++) L += g_pl[bh0 + sp];
        s_cbar[tid] = a / L;
    }
    __syncthreads();

    const float* crow = content + (size_t)b * Fdim + h * Dd;
    if (tid < DU) {
        const float* Wc = Wv_u + ((size_t)h * DU) * DU + tid;
        float acc = bv_u[h * DU + tid];
        #pragma unroll 8
        for (int d = 0; d < DU; d++) acc = fmaf(s_cbar[d], Wc[d * DU], acc);
        out[(size_t)b * Fdim + h * Dd + tid] = acc + crow[tid];
    } else if (tid < Dd) {
        int e = tid - DU;
        const float* Wc = Wv_p + ((size_t)h * DP) * DP + e;
        float acc = bv_p[h * DP + e];
        #pragma unroll 8
        for (int d = 0; d < DP; d++) acc = fmaf(s_cbar[DU + d], Wc[d * DP], acc);
        out[(size_t)b * Fdim + h * Dd + tid] = acc + crow[tid];
    }
}

extern "C" void kernel_launch(void* const* d_in, const int* in_sizes, int n_in,
                              void* d_out, int out_size)
{
    const float* content = (const float*)d_in[1];
    const float* cache   = (const float*)d_in[3];
    const float* Wq_u    = (const float*)d_in[5];
    const float* bq_u    = (const float*)d_in[6];
    const float* Wk_u    = (const float*)d_in[7];
    const float* bk_u    = (const float*)d_in[8];
    const float* Wv_u    = (const float*)d_in[9];
    const float* bv_u    = (const float*)d_in[10];
    const float* Wq_p    = (const float*)d_in[11];
    const float* bq_p    = (const float*)d_in[12];
    const float* Wk_p    = (const float*)d_in[13];
    const float* bk_p    = (const float*)d_in[14];
    const float* Wv_p    = (const float*)d_in[15];
    const float* bv_p    = (const float*)d_in[16];
    const float* pos_p   = (const float*)d_in[17];
    float* out = (float*)d_out;

    prep_kernel<<<Hh, 256>>>(content, Wq_u, bq_u, Wk_u, bk_u,
                             Wq_p, bq_p, Wk_p, bk_p);

    dim3 gridB(Hh, Bn, SPLIT);
    stream_kernel<<<gridB, 256>>>(content, cache, pos_p);

    dim3 gridC(Hh, Bn);
    combine_kernel<<<gridC, 128>>>(content, Wv_u, bv_u, Wv_p, bv_p, out);
}

// round 16
// speedup vs baseline: 1.2388x; 1.2388x over previous
#include <cuda_runtime.h>
#include <math.h>

#define Hh   16
#define DU   64
#define DP   32
#define Dd   96
#define Bn   16
#define TCACHE 4095
#define TT   4096
#define WIN  512
#define Fdim 1536

#define SPLIT  2
#define ROWS_B (WIN / SPLIT)      // 256 rows per stream CTA
#define ITER_B (ROWS_B / 8 / 4)   // iterations per warp (8 warps, 4 rows/iter)

__device__ float g_qt[Bn * Hh][104];            // [0..95]=qt (pre-scaled), [96]=const
__device__ float g_pl[Bn * Hh * SPLIT];         // partial l
__device__ float g_pacc[Bn * Hh * SPLIT][Dd];   // partial acc

// ---------------- Kernel A: q projection + K-fold, smem-staged weights ----------------
// One CTA per (h,b). All weight slices (40KB) loaded in one coalesced float4 wave,
// GEMVs run from smem (29-cyc latency instead of ~600-cyc global).
__global__ __launch_bounds__(256)
void prep_kernel(const float* __restrict__ content,
                 const float* __restrict__ Wq_u, const float* __restrict__ bq_u,
                 const float* __restrict__ Wk_u, const float* __restrict__ bk_u,
                 const float* __restrict__ Wq_p, const float* __restrict__ bq_p,
                 const float* __restrict__ Wk_p, const float* __restrict__ bk_p)
{
    const int h    = blockIdx.x;
    const int b    = blockIdx.y;
    const int tid  = threadIdx.x;
    const int lane = tid & 31;

    __shared__ alignas(16) float sWqu[DU * DU];   // 16 KB
    __shared__ alignas(16) float sWqp[DP * DP];   //  4 KB
    __shared__ alignas(16) float sWku[DU * DU];   // 16 KB
    __shared__ alignas(16) float sWkp[DP * DP];   //  4 KB
    __shared__ float s_u[Dd];
    __shared__ float s_q[Dd];

    // ---- one wide load wave: 2560 float4 across 256 threads (10 each) ----
    {
        const float4* g1 = (const float4*)(Wq_u + (size_t)h * DU * DU);
        const float4* g2 = (const float4*)(Wq_p + (size_t)h * DP * DP);
        const float4* g3 = (const float4*)(Wk_u + (size_t)h * DU * DU);
        const float4* g4 = (const float4*)(Wk_p + (size_t)h * DP * DP);
        #pragma unroll
        for (int i = 0; i < 4; i++) ((float4*)sWqu)[tid + 256 * i] = g1[tid + 256 * i];
        ((float4*)sWqp)[tid & 255] = g2[tid & 255];   // 256 float4
        #pragma unroll
        for (int i = 0; i < 4; i++) ((float4*)sWku)[tid + 256 * i] = g3[tid + 256 * i];
        ((float4*)sWkp)[tid & 255] = g4[tid & 255];
    }
    if (tid < Dd) s_u[tid] = content[(size_t)b * Fdim + h * Dd + tid];
    __syncthreads();

    // ---- GEMV1: q[e] = bq[e] + sum_d u[d] * Wq[d][e]  (column access, no conflicts) ----
    if (tid < DU) {
        float acc = bq_u[h * DU + tid];
        #pragma unroll 16
        for (int d = 0; d < DU; d++) acc = fmaf(s_u[d], sWqu[d * DU + tid], acc);
        s_q[tid] = acc;
    } else if (tid < Dd) {
        int ep = tid - DU;
        float acc = bq_p[h * DP + ep];
        #pragma unroll 16
        for (int d = 0; d < DP; d++) acc = fmaf(s_u[DU + d], sWqp[d * DP + ep], acc);
        s_q[tid] = acc;
    }
    __syncthreads();

    // ---- GEMV2: qt[d] = inv * sum_e Wk[d][e] * q[e]  (row access, lane-rotated) ----
    const float inv = 1.0f / sqrtf((float)Dd);
    if (tid < DU) {
        const float* row = sWku + tid * DU;
        float acc = 0.f;
        #pragma unroll 16
        for (int ee = 0; ee < DU; ee++) {
            int e = (ee + lane) & (DU - 1);
            acc = fmaf(row[e], s_q[e], acc);
        }
        g_qt[b * Hh + h][tid] = acc * inv;
    } else if (tid < Dd) {
        const float* row = sWkp + (tid - DU) * DP;
        float acc = 0.f;
        #pragma unroll 16
        for (int ee = 0; ee < DP; ee++) {
            int e = (ee + lane) & (DP - 1);
            acc = fmaf(row[e], s_q[DU + e], acc);
        }
        g_qt[b * Hh + h][tid] = acc * inv;
    } else if (tid < 128) {
        // const term: (q . bk) * inv — warp 3, 3 elements per lane, shfl reduce
        int l3 = (tid - Dd) * 3;           // tid 96..127 -> 0,3,...,93
        float acc = 0.f;
        #pragma unroll
        for (int j = 0; j < 3; j++) {
            int e = l3 + j;
            float bk = (e < DU) ? bk_u[h * DU + e] : bk_p[h * DP + (e - DU)];
            acc = fmaf(s_q[e], bk, acc);
        }
        #pragma unroll
        for (int off = 16; off; off >>= 1)
            acc += __shfl_xor_sync(0xffffffffu, acc, off);
        if (tid == Dd) g_qt[b * Hh + h][Dd] = acc * inv;
    }
}

// ---------------- Kernel B: streaming attention over a window split ----------------
__global__ __launch_bounds__(256, 4)
void stream_kernel(const float* __restrict__ content,
                   const float* __restrict__ cache,
                   const float* __restrict__ pos_param_p)
{
    const int h     = blockIdx.x;
    const int b     = blockIdx.y;
    const int split = blockIdx.z;
    const int tid   = threadIdx.x;
    const int lane  = tid & 31;
    const int w     = tid >> 5;
    const int qq    = lane >> 3;
    const int s     = lane & 7;
    const int s4    = s * 4;

    __shared__ alignas(16) float s_qt[104];
    __shared__ float s_bias[ROWS_B];
    __shared__ float s_gl[32];
    __shared__ alignas(16) float s_gacc[32][Dd];

    const float pp = *pos_param_p;

    if (tid < 97) s_qt[tid] = g_qt[b * Hh + h][tid];

    // bias for this split's rows (time_mask is a uniform shift -> ignored)
    for (int p = tid; p < ROWS_B; p += 256) {
        int n = (WIN - 1) - (split * ROWS_B + p);
        float bucket;
        if (n < 16)        bucket = (float)n;
        else if (n >= 113) bucket = 31.0f;
        else {
            int bb = 16 + (int)(__logf((float)n * 0.0625f) * 7.69365658f);
            bucket = (float)bb;
        }
        s_bias[p] = -pp * bucket;
    }
    __syncthreads();

    const float4* q4 = (const float4*)s_qt;
    const float4  qtA = q4[s], qtB = q4[8 + s], qtC = q4[16 + s];
    const float   sc  = s_qt[Dd];
    const float*  crow  = content + (size_t)b * Fdim + h * Dd;
    const float*  cbase = cache   + ((size_t)b * TCACHE) * Fdim + h * Dd;
    const int     base  = (TT - WIN) + split * ROWS_B + w * (ROWS_B / 8);

    float l = 0.f;
    float4 aA = {0,0,0,0}, aB = {0,0,0,0}, aC = {0,0,0,0};

    const float* r0;
    {
        int j = base + qq;
        r0 = (j < TCACHE) ? (cbase + (size_t)j * Fdim) : crow;
    }
    float4 nva = *(const float4*)(r0 + s4);
    float4 nvb = *(const float4*)(r0 + 32 + s4);
    float4 nvc = *(const float4*)(r0 + 64 + s4);

    #pragma unroll 2
    for (int i = 0; i < ITER_B; i++) {
        float4 va = nva, vb = nvb, vc = nvc;
        if (i < ITER_B - 1) {
            int j = base + (i + 1) * 4 + qq;
            const float* r = (j < TCACHE) ? (cbase + (size_t)j * Fdim) : crow;
            nva = *(const float4*)(r + s4);
            nvb = *(const float4*)(r + 32 + s4);
            nvc = *(const float4*)(r + 64 + s4);
        }
        float x;
        x = va.x * qtA.x;          x = fmaf(va.y, qtA.y, x);
        x = fmaf(va.z, qtA.z, x);  x = fmaf(va.w, qtA.w, x);
        x = fmaf(vb.x, qtB.x, x);  x = fmaf(vb.y, qtB.y, x);
        x = fmaf(vb.z, qtB.z, x);  x = fmaf(vb.w, qtB.w, x);
        x = fmaf(vc.x, qtC.x, x);  x = fmaf(vc.y, qtC.y, x);
        x = fmaf(vc.z, qtC.z, x);  x = fmaf(vc.w, qtC.w, x);
        x += __shfl_xor_sync(0xffffffffu, x, 1);
        x += __shfl_xor_sync(0xffffffffu, x, 2);
        x += __shfl_xor_sync(0xffffffffu, x, 4);

        float e = __expf(x + sc + s_bias[w * (ROWS_B / 8) + i * 4 + qq]);
        l += e;
        aA.x = fmaf(e, va.x, aA.x); aA.y = fmaf(e, va.y, aA.y);
        aA.z = fmaf(e, va.z, aA.z); aA.w = fmaf(e, va.w, aA.w);
        aB.x = fmaf(e, vb.x, aB.x); aB.y = fmaf(e, vb.y, aB.y);
        aB.z = fmaf(e, vb.z, aB.z); aB.w = fmaf(e, vb.w, aB.w);
        aC.x = fmaf(e, vc.x, aC.x); aC.y = fmaf(e, vc.y, aC.y);
        aC.z = fmaf(e, vc.z, aC.z); aC.w = fmaf(e, vc.w, aC.w);
    }

    const int g = (w << 2) | qq;
    if (s == 0) s_gl[g] = l;
    *(float4*)&s_gacc[g][s4]      = aA;
    *(float4*)&s_gacc[g][32 + s4] = aB;
    *(float4*)&s_gacc[g][64 + s4] = aC;
    __syncthreads();

    const int bh = (b * Hh + h) * SPLIT + split;
    if (tid < Dd) {
        float a = 0.f;
        #pragma unroll
        for (int gg = 0; gg < 32; gg++) a += s_gacc[gg][tid];
        g_pacc[bh][tid] = a;
    } else if (tid == Dd) {
        float L = 0.f;
        #pragma unroll
        for (int gg = 0; gg < 32; gg++) L += s_gl[gg];
        g_pl[bh] = L;
    }
}

// ---------------- Kernel C: combine + V-projection + residual ----------------
__global__ __launch_bounds__(128)
void combine_kernel(const float* __restrict__ content,
                    const float* __restrict__ Wv_u, const float* __restrict__ bv_u,
                    const float* __restrict__ Wv_p, const float* __restrict__ bv_p,
                    float* __restrict__ out)
{
    const int h   = blockIdx.x;
    const int b   = blockIdx.y;
    const int tid = threadIdx.x;

    __shared__ float s_cbar[Dd];

    const int bh0 = (b * Hh + h) * SPLIT;
    if (tid < Dd) {
        float a = 0.f, L = 0.f;
        #pragma unroll
        for (int sp = 0; sp < SPLIT; sp++) a += g_pacc[bh0 + sp][tid];
        #pragma unroll
        for (int sp = 0; sp < SPLIT; sp++) L += g_pl[bh0 + sp];
        s_cbar[tid] = a / L;
    }
    __syncthreads();

    const float* crow = content + (size_t)b * Fdim + h * Dd;
    if (tid < DU) {
        const float* Wc = Wv_u + ((size_t)h * DU) * DU + tid;
        float acc = bv_u[h * DU + tid];
        #pragma unroll 8
        for (int d = 0; d < DU; d++) acc = fmaf(s_cbar[d], Wc[d * DU], acc);
        out[(size_t)b * Fdim + h * Dd + tid] = acc + crow[tid];
    } else if (tid < Dd) {
        int e = tid - DU;
        const float* Wc = Wv_p + ((size_t)h * DP) * DP + e;
        float acc = bv_p[h * DP + e];
        #pragma unroll 8
        for (int d = 0; d < DP; d++) acc = fmaf(s_cbar[DU + d], Wc[d * DP], acc);
        out[(size_t)b * Fdim + h * Dd + tid] = acc + crow[tid];
    }
}

extern "C" void kernel_launch(void* const* d_in, const int* in_sizes, int n_in,
                              void* d_out, int out_size)
{
    const float* content = (const float*)d_in[1];
    const float* cache   = (const float*)d_in[3];
    const float* Wq_u    = (const float*)d_in[5];
    const float* bq_u    = (const float*)d_in[6];
    const float* Wk_u    = (const float*)d_in[7];
    const float* bk_u    = (const float*)d_in[8];
    const float* Wv_u    = (const float*)d_in[9];
    const float* bv_u    = (const float*)d_in[10];
    const float* Wq_p    = (const float*)d_in[11];
    const float* bq_p    = (const float*)d_in[12];
    const float* Wk_p    = (const float*)d_in[13];
    const float* bk_p    = (const float*)d_in[14];
    const float* Wv_p    = (const float*)d_in[15];
    const float* bv_p    = (const float*)d_in[16];
    const float* pos_p   = (const float*)d_in[17];
    float* out = (float*)d_out;

    dim3 gridA(Hh, Bn);
    prep_kernel<<<gridA, 256>>>(content, Wq_u, bq_u, Wk_u, bk_u,
                                Wq_p, bq_p, Wk_p, bk_p);

    dim3 gridB(Hh, Bn, SPLIT);
    stream_kernel<<<gridB, 256>>>(content, cache, pos_p);

    dim3 gridC(Hh, Bn);
    combine_kernel<<<gridC, 128>>>(content, Wv_u, bv_u, Wv_p, bv_p, out);
}

// round 17
// speedup vs baseline: 1.6642x; 1.3434x over previous
#include <cuda_runtime.h>
#include <math.h>

#define Hh   16
#define DU   64
#define DP   32
#define Dd   96
#define Bn   16
#define TCACHE 4095
#define TT   4096
#define WIN  512
#define Fdim 1536

// dynamic smem layout (floats)
#define OFF_WU    0        // 4096: Wq_u, later Wv_u
#define OFF_WP    4096     // 1024: Wq_p, later Wv_p
#define OFF_KU    5120     // 4096: Wk_u
#define OFF_KP    9216     // 1024: Wk_p
#define OFF_U     10240    // 96
#define OFF_Q     10336    // 96
#define OFF_QT    10432    // 104 (16B aligned)
#define OFF_BIAS  10536    // 512
#define OFF_GL    11048    // 32
#define OFF_GACC  11080    // 32*96 (16B aligned, row stride 384B)
#define OFF_CBAR  14152    // 96
#define SMEM_F    14248    // 56992 bytes

__global__ __launch_bounds__(256, 2)
void bichan_attn_kernel(const float* __restrict__ content,
                        const float* __restrict__ cache,
                        const float* __restrict__ Wq_u, const float* __restrict__ bq_u,
                        const float* __restrict__ Wk_u, const float* __restrict__ bk_u,
                        const float* __restrict__ Wv_u, const float* __restrict__ bv_u,
                        const float* __restrict__ Wq_p, const float* __restrict__ bq_p,
                        const float* __restrict__ Wk_p, const float* __restrict__ bk_p,
                        const float* __restrict__ Wv_p, const float* __restrict__ bv_p,
                        const float* __restrict__ pos_param_p,
                        float* __restrict__ out)
{
    extern __shared__ __align__(16) float sm[];
    float* sWu   = sm + OFF_WU;
    float* sWp   = sm + OFF_WP;
    float* sKu   = sm + OFF_KU;
    float* sKp   = sm + OFF_KP;
    float* s_u   = sm + OFF_U;
    float* s_q   = sm + OFF_Q;
    float* s_qt  = sm + OFF_QT;
    float* s_bias= sm + OFF_BIAS;
    float* s_gl  = sm + OFF_GL;
    float* s_gacc= sm + OFF_GACC;     // [32][96]
    float* s_cbar= sm + OFF_CBAR;

    const int h    = blockIdx.x;
    const int b    = blockIdx.y;
    const int tid  = threadIdx.x;
    const int lane = tid & 31;
    const int w    = tid >> 5;
    const int qq   = lane >> 3;
    const int s    = lane & 7;
    const int s4   = s * 4;

    const float  pp   = *pos_param_p;
    const float* crow = content + (size_t)b * Fdim + h * Dd;

    // prefetch bias value for GEMV1 (overlaps with weight wave)
    float bqv = 0.f;
    if (tid < DU)      bqv = bq_u[h * DU + tid];
    else if (tid < Dd) bqv = bq_p[h * DP + (tid - DU)];

    // ---- weight wave 1: Wq + Wk (2560 float4, 10 per thread) ----
    {
        const float4* g1 = (const float4*)(Wq_u + (size_t)h * DU * DU);
        const float4* g2 = (const float4*)(Wq_p + (size_t)h * DP * DP);
        const float4* g3 = (const float4*)(Wk_u + (size_t)h * DU * DU);
        const float4* g4 = (const float4*)(Wk_p + (size_t)h * DP * DP);
        #pragma unroll
        for (int i = 0; i < 4; i++) ((float4*)sWu)[tid + 256 * i] = g1[tid + 256 * i];
        ((float4*)sWp)[tid] = g2[tid];
        #pragma unroll
        for (int i = 0; i < 4; i++) ((float4*)sKu)[tid + 256 * i] = g3[tid + 256 * i];
        ((float4*)sKp)[tid] = g4[tid];
    }
    if (tid < Dd) s_u[tid] = crow[tid];

    // bias table (time_mask is a uniform shift -> ignored; fp32 bucket exact)
    for (int p = tid; p < WIN; p += 256) {
        int n = (WIN - 1) - p;
        float bucket;
        if (n < 16)        bucket = (float)n;
        else if (n >= 113) bucket = 31.0f;
        else {
            int bb = 16 + (int)(__logf((float)n * 0.0625f) * 7.69365658f);
            bucket = (float)bb;
        }
        s_bias[p] = -pp * bucket;
    }
    __syncthreads();

    // ---- GEMV1 from smem: q[e] = bq[e] + sum_d u[d] * Wq[d][e] ----
    if (tid < DU) {
        float acc = bqv;
        #pragma unroll 16
        for (int d = 0; d < DU; d++) acc = fmaf(s_u[d], sWu[d * DU + tid], acc);
        s_q[tid] = acc;
    } else if (tid < Dd) {
        int ep = tid - DU;
        float acc = bqv;
        #pragma unroll 16
        for (int d = 0; d < DP; d++) acc = fmaf(s_u[DU + d], sWp[d * DP + ep], acc);
        s_q[tid] = acc;
    }
    __syncthreads();

    // ---- GEMV2 from smem: qt[d] = inv * sum_e Wk[d][e] * q[e] (lane-rotated rows) ----
    const float inv = 1.0f / sqrtf((float)Dd);
    if (tid < DU) {
        const float* row = sKu + tid * DU;
        float acc = 0.f;
        #pragma unroll 16
        for (int ee = 0; ee < DU; ee++) {
            int e = (ee + lane) & (DU - 1);
            acc = fmaf(row[e], s_q[e], acc);
        }
        s_qt[tid] = acc * inv;
    } else if (tid < Dd) {
        const float* row = sKp + (tid - DU) * DP;
        float acc = 0.f;
        #pragma unroll 16
        for (int ee = 0; ee < DP; ee++) {
            int e = (ee + lane) & (DP - 1);
            acc = fmaf(row[e], s_q[DU + e], acc);
        }
        s_qt[tid] = acc * inv;
    } else if (tid < 128) {
        // const term: (q . bk) * inv via warp 3 + shfl reduce
        int l3 = (tid - Dd) * 3;
        float acc = 0.f;
        #pragma unroll
        for (int j = 0; j < 3; j++) {
            int e = l3 + j;
            float bk = (e < DU) ? bk_u[h * DU + e] : bk_p[h * DP + (e - DU)];
            acc = fmaf(s_q[e], bk, acc);
        }
        #pragma unroll
        for (int off = 16; off; off >>= 1)
            acc += __shfl_xor_sync(0xffffffffu, acc, off);
        if (tid == Dd) s_qt[103] = acc * inv;   // stash const at [103]
    }
    __syncthreads();

    // ---- weight wave 2: Wv into the Wq buffers (completes under the mainloop) ----
    {
        const float4* g5 = (const float4*)(Wv_u + (size_t)h * DU * DU);
        const float4* g6 = (const float4*)(Wv_p + (size_t)h * DP * DP);
        #pragma unroll
        for (int i = 0; i < 4; i++) ((float4*)sWu)[tid + 256 * i] = g5[tid + 256 * i];
        ((float4*)sWp)[tid] = g6[tid];
    }

    // ---- main pass: shift-free softmax accumulation (validated R13 structure) ----
    const float4* q4 = (const float4*)s_qt;
    const float4  qtA = q4[s], qtB = q4[8 + s], qtC = q4[16 + s];
    const float   sc  = s_qt[103];
    const float*  cbase = cache + ((size_t)b * TCACHE) * Fdim + h * Dd;

    float l = 0.f;
    float4 aA = {0,0,0,0}, aB = {0,0,0,0}, aC = {0,0,0,0};

    const float* r0;
    {
        int j = (TT - WIN) + w * 64 + qq;
        r0 = (j < TCACHE) ? (cbase + (size_t)j * Fdim) : crow;
    }
    float4 nva = *(const float4*)(r0 + s4);
    float4 nvb = *(const float4*)(r0 + 32 + s4);
    float4 nvc = *(const float4*)(r0 + 64 + s4);

    #pragma unroll 2
    for (int i = 0; i < 16; i++) {
        float4 va = nva, vb = nvb, vc = nvc;
        if (i < 15) {
            int j = (TT - WIN) + w * 64 + (i + 1) * 4 + qq;
            const float* r = (j < TCACHE) ? (cbase + (size_t)j * Fdim) : crow;
            nva = *(const float4*)(r + s4);
            nvb = *(const float4*)(r + 32 + s4);
            nvc = *(const float4*)(r + 64 + s4);
        }
        float x;
        x = va.x * qtA.x;          x = fmaf(va.y, qtA.y, x);
        x = fmaf(va.z, qtA.z, x);  x = fmaf(va.w, qtA.w, x);
        x = fmaf(vb.x, qtB.x, x);  x = fmaf(vb.y, qtB.y, x);
        x = fmaf(vb.z, qtB.z, x);  x = fmaf(vb.w, qtB.w, x);
        x = fmaf(vc.x, qtC.x, x);  x = fmaf(vc.y, qtC.y, x);
        x = fmaf(vc.z, qtC.z, x);  x = fmaf(vc.w, qtC.w, x);
        x += __shfl_xor_sync(0xffffffffu, x, 1);
        x += __shfl_xor_sync(0xffffffffu, x, 2);
        x += __shfl_xor_sync(0xffffffffu, x, 4);

        float e = __expf(x + sc + s_bias[w * 64 + i * 4 + qq]);
        l += e;
        aA.x = fmaf(e, va.x, aA.x); aA.y = fmaf(e, va.y, aA.y);
        aA.z = fmaf(e, va.z, aA.z); aA.w = fmaf(e, va.w, aA.w);
        aB.x = fmaf(e, vb.x, aB.x); aB.y = fmaf(e, vb.y, aB.y);
        aB.z = fmaf(e, vb.z, aB.z); aB.w = fmaf(e, vb.w, aB.w);
        aC.x = fmaf(e, vc.x, aC.x); aC.y = fmaf(e, vc.y, aC.y);
        aC.z = fmaf(e, vc.z, aC.z); aC.w = fmaf(e, vc.w, aC.w);
    }

    // ---- write 32 partial groups ----
    const int g = (w << 2) | qq;
    if (s == 0) s_gl[g] = l;
    *(float4*)&s_gacc[g * Dd + s4]      = aA;
    *(float4*)&s_gacc[g * Dd + 32 + s4] = aB;
    *(float4*)&s_gacc[g * Dd + 64 + s4] = aC;
    __syncthreads();

    // ---- combine 32 groups (plain sums — shift-free) ----
    if (tid < Dd) {
        float L = 0.f, a = 0.f;
        #pragma unroll
        for (int gg = 0; gg < 32; gg++) {
            L += s_gl[gg];
            a += s_gacc[gg * Dd + tid];
        }
        s_cbar[tid] = a / L;
    }
    __syncthreads();

    // ---- output projection from smem-staged Wv + residual ----
    if (tid < DU) {
        float acc = bv_u[h * DU + tid];
        #pragma unroll 16
        for (int d = 0; d < DU; d++) acc = fmaf(s_cbar[d], sWu[d * DU + tid], acc);
        out[(size_t)b * Fdim + h * Dd + tid] = acc + s_u[tid];
    } else if (tid < Dd) {
        int e = tid - DU;
        float acc = bv_p[h * DP + e];
        #pragma unroll 16
        for (int d = 0; d < DP; d++) acc = fmaf(s_cbar[DU + d], sWp[d * DP + e], acc);
        out[(size_t)b * Fdim + h * Dd + tid] = acc + s_u[tid];
    }
}

extern "C" void kernel_launch(void* const* d_in, const int* in_sizes, int n_in,
                              void* d_out, int out_size)
{
    const float* content = (const float*)d_in[1];
    const float* cache   = (const float*)d_in[3];
    const float* Wq_u    = (const float*)d_in[5];
    const float* bq_u    = (const float*)d_in[6];
    const float* Wk_u    = (const float*)d_in[7];
    const float* bk_u    = (const float*)d_in[8];
    const float* Wv_u    = (const float*)d_in[9];
    const float* bv_u    = (const float*)d_in[10];
    const float* Wq_p    = (const float*)d_in[11];
    const float* bq_p    = (const float*)d_in[12];
    const float* Wk_p    = (const float*)d_in[13];
    const float* bk_p    = (const float*)d_in[14];
    const float* Wv_p    = (const float*)d_in[15];
    const float* bv_p    = (const float*)d_in[16];
    const float* pos_p   = (const float*)d_in[17];
    float* out = (float*)d_out;

    const int dyn_smem = SMEM_F * (int)sizeof(float);   // 56992 B
    cudaFuncSetAttribute(bichan_attn_kernel,
                         cudaFuncAttributeMaxDynamicSharedMemorySize, dyn_smem);

    dim3 grid(Hh, Bn);
    bichan_attn_kernel<<<grid, 256, dyn_smem>>>(content, cache,
                                                Wq_u, bq_u, Wk_u, bk_u, Wv_u, bv_u,
                                                Wq_p, bq_p, Wk_p, bk_p, Wv_p, bv_p,
                                                pos_p, out);
}